// round 11
// baseline (speedup 1.0000x reference)
#include <cuda_runtime.h>
#include <cstdint>
#include <math.h>

// Problem constants: B=8, K=1024, L=1024, D=1024, O=6, E=128
#define Bb 8
#define Kk 1024
#define Ll 1024
#define Dd 1024
#define Oo 6
#define Ee 128

// ---------------------------------------------------------------------------
// Scratch (device globals: allocation-free, persistent; every element is
// rewritten on every launch so graph replays are deterministic).
// ---------------------------------------------------------------------------
__device__ __align__(16) float g_UsumP[Bb * 8 * Dd];
__device__ __align__(16) float g_Wv   [Bb * Oo * Dd];
__device__ __align__(16) float g_Vacc [Bb * Oo * Ee];
__device__ __align__(16) float g_vcur [Bb * Oo * Ee];
__device__ __align__(16) float g_probs[Bb * Kk * Oo];
__device__ __align__(16) float g_UpP  [Bb * 32 * Oo * Dd];
__device__ int g_mask_u8;

// ---------------------------------------------------------------------------
// K1: Usum partials + mask-dtype probe (block 0).
// ---------------------------------------------------------------------------
__global__ void k_usum(const float* __restrict__ u,
                       const unsigned char* __restrict__ m) {
    int t  = threadIdx.x;

    if (blockIdx.x == 0 && blockIdx.y == 0 && blockIdx.z == 0) {
        __shared__ int f;
        if (t == 0) f = 0;
        __syncthreads();
        int loc = 0;
        for (int p = t; p < Bb * Kk; p += blockDim.x)
            if ((p & 3) && m[p]) loc = 1;
        if (loc) atomicOr(&f, 1);
        __syncthreads();
        if (t == 0) g_mask_u8 = f;
    }

    int d4 = blockIdx.x * 128 + t;
    int ks = blockIdx.y;
    int b  = blockIdx.z;
    const float4* p = reinterpret_cast<const float4*>(u)
                    + ((size_t)(b * Kk + ks * 128)) * 256 + d4;
    float4 s = make_float4(0.f, 0.f, 0.f, 0.f);
#pragma unroll 8
    for (int k = 0; k < 128; k++) {
        float4 v = p[(size_t)k * 256];
        s.x += v.x; s.y += v.y; s.z += v.z; s.w += v.w;
    }
    reinterpret_cast<float4*>(g_UsumP)[(b * 8 + ks) * 256 + d4] = s;
}

// ---------------------------------------------------------------------------
// K2: v0 = squash((1/6) * Usum . W).  grid (O, B), 512 threads.
// ---------------------------------------------------------------------------
__global__ __launch_bounds__(512) void k_v0(const float* __restrict__ W) {
    int t = threadIdx.x;
    int o = blockIdx.x, b = blockIdx.y;
    __shared__ float Us[Dd];
    __shared__ float part[4][Ee];
    __shared__ float red[4];

    for (int d = t; d < Dd; d += 512) {
        float s = 0.f;
#pragma unroll
        for (int ks = 0; ks < 8; ks++) s += g_UsumP[(b * 8 + ks) * Dd + d];
        Us[d] = s;
    }
    __syncthreads();

    int e = t & 127, ws = t >> 7;
    const float* Wp = W + (size_t)o * Dd * Ee + e;
    float acc = 0.f;
#pragma unroll 16
    for (int dd = 0; dd < 256; dd++) {
        int d = ws * 256 + dd;
        acc += Us[d] * Wp[(size_t)d * Ee];
    }
    part[ws][e] = acc;
    __syncthreads();

    float v = 0.f;
    if (t < 128) {
        float s = (part[0][t] + part[1][t] + part[2][t] + part[3][t]) * (1.f / 6.f);
        v = s;
        float x = s * s;
#pragma unroll
        for (int sh = 16; sh; sh >>= 1) x += __shfl_xor_sync(0xffffffffu, x, sh);
        if ((t & 31) == 0) red[t >> 5] = x;
    }
    __syncthreads();
    if (t < 128) {
        float sq = red[0] + red[1] + red[2] + red[3];
        float f  = sq / (1.f + sq) / (sqrtf(sq) + 1e-8f);
        g_Vacc[(b * Oo + o) * Ee + t] = f * v;
    }
}

// ---------------------------------------------------------------------------
// K3: Wv[b,o,d] = sum_e W[o,d,e] * Vacc[b,o,e].  grid (128, O), 256 thr.
// ---------------------------------------------------------------------------
__global__ __launch_bounds__(256) void k_wv(const float* __restrict__ W) {
    __shared__ float4 Vs[Bb][32];
    int t = threadIdx.x, w = t >> 5, lane = t & 31;
    int o = blockIdx.y;

    {
        int b = t >> 5, i = t & 31;
        Vs[b][i] = reinterpret_cast<const float4*>(g_Vacc)[(b * Oo + o) * 32 + i];
    }
    __syncthreads();

    int d = blockIdx.x * 8 + w;
    float4 w4 = reinterpret_cast<const float4*>(W)[((size_t)o * Dd + d) * 32 + lane];

    float acc[8];
#pragma unroll
    for (int b = 0; b < 8; b++) {
        float4 v4 = Vs[b][lane];
        acc[b] = w4.x * v4.x + w4.y * v4.y + w4.z * v4.z + w4.w * v4.w;
    }
#pragma unroll
    for (int sh = 16; sh; sh >>= 1) {
#pragma unroll
        for (int b = 0; b < 8; b++)
            acc[b] += __shfl_xor_sync(0xffffffffu, acc[b], sh);
    }
    if (lane < 8)
        g_Wv[(lane * Oo + o) * Dd + d] = acc[lane];
}

// ---------------------------------------------------------------------------
// Shared softmax helper (device inline)
// ---------------------------------------------------------------------------
__device__ __forceinline__ void softmax6(const float lg[6], bool masked, float p[6]) {
    if (masked) {
#pragma unroll
        for (int o = 0; o < 6; o++) p[o] = 1.f / 6.f;
    } else {
        float m = lg[0];
#pragma unroll
        for (int o = 1; o < 6; o++) m = fmaxf(m, lg[o]);
        float s = 0.f;
#pragma unroll
        for (int o = 0; o < 6; o++) { p[o] = expf(lg[o] - m); s += p[o]; }
        float inv = 1.f / s;
#pragma unroll
        for (int o = 0; o < 6; o++) p[o] *= inv;
    }
}

// ---------------------------------------------------------------------------
// K4a: FUSED route (iteration 1): logits -> softmax -> probs -> Up partials,
// with the 128KB u-tile staged in dynamic smem during phase 1 so phase 2
// reads smem instead of a second global pass. grid (32, B), 256 threads.
// Dynamic smem: u tile 8192 f4 + Wv 1536 f4 = 155648 B.
// ---------------------------------------------------------------------------
__global__ __launch_bounds__(256) void k_route_full(const float* __restrict__ u,
                                                    const void*  __restrict__ maskp) {
    extern __shared__ __align__(16) float4 sm4[];
    float4* u4s = sm4;              // [32*256]
    float4* wv4 = sm4 + 32 * 256;   // [6*256]
    __shared__ float probs_s[32 * Oo];

    int t = threadIdx.x;
    int w = t >> 5, lane = t & 31;
    int b  = blockIdx.y;
    int k0 = blockIdx.x * 32;

    {
        const float4* ss = reinterpret_cast<const float4*>(g_Wv + (size_t)b * Oo * Dd);
#pragma unroll
        for (int i = 0; i < 6; i++) wv4[t + 256 * i] = ss[t + 256 * i];
    }
    __syncthreads();

    // Phase 1: logits for 4 k per warp; stage u into smem as we read it.
    int kw = k0 + w * 4;
    float lg[4][6];
#pragma unroll
    for (int kk = 0; kk < 4; kk++)
#pragma unroll
        for (int o = 0; o < 6; o++) lg[kk][o] = 0.f;

    const float4* up4 = reinterpret_cast<const float4*>(u) + (size_t)(b * Kk + kw) * 256;
#pragma unroll
    for (int j = 0; j < 8; j++) {
        int di = j * 32 + lane;
        float4 wv[6];
#pragma unroll
        for (int o = 0; o < 6; o++) wv[o] = wv4[o * 256 + di];
#pragma unroll
        for (int kk = 0; kk < 4; kk++) {
            float4 uv = up4[(size_t)kk * 256 + di];
            u4s[(w * 4 + kk) * 256 + di] = uv;
#pragma unroll
            for (int o = 0; o < 6; o++)
                lg[kk][o] += uv.x * wv[o].x + uv.y * wv[o].y
                           + uv.z * wv[o].z + uv.w * wv[o].w;
        }
    }
#pragma unroll
    for (int sh = 16; sh; sh >>= 1)
#pragma unroll
        for (int kk = 0; kk < 4; kk++)
#pragma unroll
            for (int o = 0; o < 6; o++)
                lg[kk][o] += __shfl_xor_sync(0xffffffffu, lg[kk][o], sh);

    int u8 = g_mask_u8;
    if (lane == 0) {
#pragma unroll
        for (int kk = 0; kk < 4; kk++) {
            int k = kw + kk;
            bool masked = u8 ? (((const unsigned char*)maskp)[b * Kk + k] != 0)
                             : (((const int*)maskp)[b * Kk + k] != 0);
            float p[6];
            softmax6(lg[kk], masked, p);
#pragma unroll
            for (int o = 0; o < 6; o++) probs_s[(w * 4 + kk) * 6 + o] = p[o];
        }
    }
    __syncthreads();   // probs ready AND u tile fully staged

    if (t < 192) g_probs[(size_t)(b * Kk + k0) * 6 + t] = probs_s[t];

    // Phase 2: Up partials from smem-staged u.
    float4 acc4[6];
#pragma unroll
    for (int o = 0; o < 6; o++) acc4[o] = make_float4(0.f, 0.f, 0.f, 0.f);

#pragma unroll 4
    for (int kk = 0; kk < 32; kk++) {
        float4 uv = u4s[kk * 256 + t];
        float pv[6];
#pragma unroll
        for (int o = 0; o < 6; o++) pv[o] = probs_s[kk * 6 + o];
#pragma unroll
        for (int o = 0; o < 6; o++) {
            acc4[o].x += pv[o] * uv.x;
            acc4[o].y += pv[o] * uv.y;
            acc4[o].z += pv[o] * uv.z;
            acc4[o].w += pv[o] * uv.w;
        }
    }
    float4* upp4 = reinterpret_cast<float4*>(
        g_UpP + ((size_t)(b * 32 + blockIdx.x) * Oo) * Dd);
#pragma unroll
    for (int o = 0; o < 6; o++) upp4[o * 256 + t] = acc4[o];
}

// ---------------------------------------------------------------------------
// K4b: logits-only route (iteration 2). Produces FINAL probs so the probs
// broadcast can start immediately; Up is computed concurrently in k_route_up.
// ---------------------------------------------------------------------------
__global__ __launch_bounds__(256) void k_route_logits(const float* __restrict__ u,
                                                      const void*  __restrict__ maskp) {
    int t = threadIdx.x;
    int w = t >> 5, lane = t & 31;
    int b  = blockIdx.y;
    int k0 = blockIdx.x * 32;

    __shared__ __align__(16) float Wv_s[Oo * Dd];
    __shared__ float probs_s[32 * Oo];

    {
        float4*       ds = reinterpret_cast<float4*>(Wv_s);
        const float4* ss = reinterpret_cast<const float4*>(g_Wv + (size_t)b * Oo * Dd);
#pragma unroll
        for (int i = 0; i < 6; i++) ds[t + 256 * i] = ss[t + 256 * i];
    }
    __syncthreads();

    int kw = k0 + w * 4;
    float lg[4][6];
#pragma unroll
    for (int kk = 0; kk < 4; kk++)
#pragma unroll
        for (int o = 0; o < 6; o++) lg[kk][o] = 0.f;

    const float4* up4 = reinterpret_cast<const float4*>(u) + (size_t)(b * Kk + kw) * 256;
    const float4* wv4 = reinterpret_cast<const float4*>(Wv_s);
#pragma unroll
    for (int j = 0; j < 8; j++) {
        int di = j * 32 + lane;
        float4 wv[6];
#pragma unroll
        for (int o = 0; o < 6; o++) wv[o] = wv4[o * 256 + di];
#pragma unroll
        for (int kk = 0; kk < 4; kk++) {
            float4 uv = up4[(size_t)kk * 256 + di];
#pragma unroll
            for (int o = 0; o < 6; o++)
                lg[kk][o] += uv.x * wv[o].x + uv.y * wv[o].y
                           + uv.z * wv[o].z + uv.w * wv[o].w;
        }
    }
#pragma unroll
    for (int sh = 16; sh; sh >>= 1)
#pragma unroll
        for (int kk = 0; kk < 4; kk++)
#pragma unroll
            for (int o = 0; o < 6; o++)
                lg[kk][o] += __shfl_xor_sync(0xffffffffu, lg[kk][o], sh);

    int u8 = g_mask_u8;
    if (lane == 0) {
#pragma unroll
        for (int kk = 0; kk < 4; kk++) {
            int k = kw + kk;
            bool masked = u8 ? (((const unsigned char*)maskp)[b * Kk + k] != 0)
                             : (((const int*)maskp)[b * Kk + k] != 0);
            float p[6];
            softmax6(lg[kk], masked, p);
#pragma unroll
            for (int o = 0; o < 6; o++) probs_s[(w * 4 + kk) * 6 + o] = p[o];
        }
    }
    __syncthreads();
    if (t < 192) g_probs[(size_t)(b * Kk + k0) * 6 + t] = probs_s[t];
}

// ---------------------------------------------------------------------------
// K4c: Up partials from stored probs (iteration 2, overlaps bcast_probs).
// ---------------------------------------------------------------------------
__global__ __launch_bounds__(256) void k_route_up(const float* __restrict__ u) {
    int t  = threadIdx.x;
    int b  = blockIdx.y;
    int k0 = blockIdx.x * 32;

    __shared__ float probs_s[32 * Oo];
    if (t < 192) probs_s[t] = g_probs[(size_t)(b * Kk + k0) * 6 + t];
    __syncthreads();

    float4 acc4[6];
#pragma unroll
    for (int o = 0; o < 6; o++) acc4[o] = make_float4(0.f, 0.f, 0.f, 0.f);

    const float4* ub4 = reinterpret_cast<const float4*>(u) + (size_t)(b * Kk + k0) * 256;
#pragma unroll 4
    for (int kk = 0; kk < 32; kk++) {
        float4 uv = ub4[(size_t)kk * 256 + t];
        float pv[6];
#pragma unroll
        for (int o = 0; o < 6; o++) pv[o] = probs_s[kk * 6 + o];
#pragma unroll
        for (int o = 0; o < 6; o++) {
            acc4[o].x += pv[o] * uv.x;
            acc4[o].y += pv[o] * uv.y;
            acc4[o].z += pv[o] * uv.z;
            acc4[o].w += pv[o] * uv.w;
        }
    }
    float4* upp4 = reinterpret_cast<float4*>(
        g_UpP + ((size_t)(b * 32 + blockIdx.x) * Oo) * Dd);
#pragma unroll
    for (int o = 0; o < 6; o++) upp4[o * 256 + t] = acc4[o];
}

// ---------------------------------------------------------------------------
// K6: v_i = squash(Up . W); Vacc += v_i; store v_i.  grid (O, B), 512 thr.
// ---------------------------------------------------------------------------
__global__ __launch_bounds__(512) void k_vi(const float* __restrict__ W) {
    int t = threadIdx.x;
    int o = blockIdx.x, b = blockIdx.y;
    __shared__ float Up_s[Dd];
    __shared__ float part[4][Ee];
    __shared__ float red[4];

    for (int d = t; d < Dd; d += 512) {
        float s = 0.f;
#pragma unroll 8
        for (int kt = 0; kt < 32; kt++)
            s += g_UpP[((size_t)(b * 32 + kt) * Oo + o) * Dd + d];
        Up_s[d] = s;
    }
    __syncthreads();

    int e = t & 127, ws = t >> 7;
    const float* Wp = W + (size_t)o * Dd * Ee + e;
    float acc = 0.f;
#pragma unroll 16
    for (int dd = 0; dd < 256; dd++) {
        int d = ws * 256 + dd;
        acc += Up_s[d] * Wp[(size_t)d * Ee];
    }
    part[ws][e] = acc;
    __syncthreads();

    float v = 0.f;
    if (t < 128) {
        float s = part[0][t] + part[1][t] + part[2][t] + part[3][t];
        v = s;
        float x = s * s;
#pragma unroll
        for (int sh = 16; sh; sh >>= 1) x += __shfl_xor_sync(0xffffffffu, x, sh);
        if ((t & 31) == 0) red[t >> 5] = x;
    }
    __syncthreads();
    if (t < 128) {
        float sq = red[0] + red[1] + red[2] + red[3];
        float f  = sq / (1.f + sq) / (sqrtf(sq) + 1e-8f);
        float vv = f * v;
        int idx = (b * Oo + o) * Ee + t;
        g_vcur[idx] = vv;
        g_Vacc[idx] += vv;
    }
}

// ---------------------------------------------------------------------------
// K7a: broadcast probs over L (201 MB). Register staging + streaming stores.
// ---------------------------------------------------------------------------
__global__ __launch_bounds__(256) void k_bcast_probs(float* __restrict__ out) {
    int t   = threadIdx.x;
    int blk = blockIdx.x;              // b * 128 + l-chunk
    int b   = blk >> 7;
    int l0  = (blk & 127) * 8;

    const float4* ps = reinterpret_cast<const float4*>(g_probs) + (size_t)b * 1536;
    float4 pr[6];
#pragma unroll
    for (int i = 0; i < 6; i++) pr[i] = __ldg(ps + t + 256 * i);

    float4* op = reinterpret_cast<float4*>(out + (size_t)Bb * Ll * Oo * Ee);
#pragma unroll
    for (int j = 0; j < 8; j++) {
        size_t bl = (size_t)b * Ll + l0 + j;
#pragma unroll
        for (int i = 0; i < 6; i++)
            __stcs(op + bl * 1536 + t + 256 * i, pr[i]);
    }
}

// ---------------------------------------------------------------------------
// K7b: broadcast outputs_v over L (25 MB).
// ---------------------------------------------------------------------------
__global__ __launch_bounds__(192) void k_bcast_v(float* __restrict__ out) {
    int t   = threadIdx.x;             // 0..191
    int blk = blockIdx.x;
    int b   = blk >> 7;
    int l0  = (blk & 127) * 8;

    float4 vv = __ldg(reinterpret_cast<const float4*>(g_vcur) + b * 192 + t);
    float4* ov = reinterpret_cast<float4*>(out);
#pragma unroll
    for (int j = 0; j < 8; j++)
        __stcs(ov + ((size_t)b * Ll + l0 + j) * 192 + t, vv);
}

// ---------------------------------------------------------------------------
// Launch. Fork-join: after the final logits kernel, the 201MB probs
// broadcast (DRAM-write-bound) runs on a side stream concurrently with the
// L2-read-bound tail (route_up -> vi -> bcast_v) on the main stream.
// ---------------------------------------------------------------------------
extern "C" void kernel_launch(void* const* d_in, const int* in_sizes, int n_in,
                              void* d_out, int out_size) {
    const float* u    = (const float*)d_in[0];
    // d_in[1] = context_sequence: unused (only its shape L matters)
    const float* W    = (const float*)d_in[2];
    const void*  mask = d_in[3];
    float* out = (float*)d_out;

    static cudaStream_t s2 = nullptr;
    static cudaEvent_t  e1 = nullptr, e2 = nullptr;
    if (s2 == nullptr) {
        cudaStreamCreateWithFlags(&s2, cudaStreamNonBlocking);
        cudaEventCreateWithFlags(&e1, cudaEventDisableTiming);
        cudaEventCreateWithFlags(&e2, cudaEventDisableTiming);
    }

    static bool attr_done = false;
    if (!attr_done) {
        cudaFuncSetAttribute(k_route_full,
                             cudaFuncAttributeMaxDynamicSharedMemorySize,
                             (32 * 256 + 6 * 256) * 16);
        attr_done = true;
    }

    k_usum<<<dim3(2, 8, 8), 128>>>(u, (const unsigned char*)mask);
    k_v0  <<<dim3(Oo, Bb), 512>>>(W);

    // Iteration 1 (fused route with smem u staging)
    k_wv        <<<dim3(Dd / 8, Oo), 256>>>(W);
    k_route_full<<<dim3(Kk / 32, Bb), 256, (32 * 256 + 6 * 256) * 16>>>(u, mask);
    k_vi        <<<dim3(Oo, Bb), 512>>>(W);

    // Iteration 2: logits first, then fork.
    k_wv          <<<dim3(Dd / 8, Oo), 256>>>(W);
    k_route_logits<<<dim3(Kk / 32, Bb), 256>>>(u, mask);

    cudaEventRecord(e1, 0);
    cudaStreamWaitEvent(s2, e1, 0);
    k_bcast_probs<<<Bb * (Ll / 8), 256, 0, s2>>>(out);   // 201 MB, overlapped
    cudaEventRecord(e2, s2);

    k_route_up<<<dim3(Kk / 32, Bb), 256>>>(u);
    k_vi      <<<dim3(Oo, Bb), 512>>>(W);
    k_bcast_v <<<Bb * (Ll / 8), 192>>>(out);

    cudaStreamWaitEvent(0, e2, 0);   // join: output complete when graph ends
}

// round 12
// speedup vs baseline: 1.0230x; 1.0230x over previous
#include <cuda_runtime.h>
#include <cstdint>
#include <math.h>

// Problem constants: B=8, K=1024, L=1024, D=1024, O=6, E=128
#define Bb 8
#define Kk 1024
#define Ll 1024
#define Dd 1024
#define Oo 6
#define Ee 128

// ---------------------------------------------------------------------------
// Scratch (device globals: allocation-free, persistent; every element is
// rewritten on every launch so graph replays are deterministic).
// ---------------------------------------------------------------------------
__device__ __align__(16) float g_UsumP[Bb * 8 * Dd];
__device__ __align__(16) float g_Wv   [Bb * Oo * Dd];
__device__ __align__(16) float g_Vacc [Bb * Oo * Ee];
__device__ __align__(16) float g_vcur [Bb * Oo * Ee];
__device__ __align__(16) float g_probs[Bb * Kk * Oo];
__device__ __align__(16) float g_UpP  [Bb * 32 * Oo * Dd];
__device__ int g_mask_u8;

// ---------------------------------------------------------------------------
// K1: Usum partials + mask-dtype probe (block 0).
// ---------------------------------------------------------------------------
__global__ void k_usum(const float* __restrict__ u,
                       const unsigned char* __restrict__ m) {
    int t  = threadIdx.x;

    if (blockIdx.x == 0 && blockIdx.y == 0 && blockIdx.z == 0) {
        __shared__ int f;
        if (t == 0) f = 0;
        __syncthreads();
        int loc = 0;
        for (int p = t; p < Bb * Kk; p += blockDim.x)
            if ((p & 3) && m[p]) loc = 1;
        if (loc) atomicOr(&f, 1);
        __syncthreads();
        if (t == 0) g_mask_u8 = f;
    }

    int d4 = blockIdx.x * 128 + t;
    int ks = blockIdx.y;
    int b  = blockIdx.z;
    const float4* p = reinterpret_cast<const float4*>(u)
                    + ((size_t)(b * Kk + ks * 128)) * 256 + d4;
    float4 s = make_float4(0.f, 0.f, 0.f, 0.f);
#pragma unroll 8
    for (int k = 0; k < 128; k++) {
        float4 v = p[(size_t)k * 256];
        s.x += v.x; s.y += v.y; s.z += v.z; s.w += v.w;
    }
    reinterpret_cast<float4*>(g_UsumP)[(b * 8 + ks) * 256 + d4] = s;
}

// ---------------------------------------------------------------------------
// K2: v0 = squash((1/6) * Usum . W).  grid (O, B), 512 threads.
// ---------------------------------------------------------------------------
__global__ __launch_bounds__(512) void k_v0(const float* __restrict__ W) {
    int t = threadIdx.x;
    int o = blockIdx.x, b = blockIdx.y;
    __shared__ float Us[Dd];
    __shared__ float part[4][Ee];
    __shared__ float red[4];

    for (int d = t; d < Dd; d += 512) {
        float s = 0.f;
#pragma unroll
        for (int ks = 0; ks < 8; ks++) s += g_UsumP[(b * 8 + ks) * Dd + d];
        Us[d] = s;
    }
    __syncthreads();

    int e = t & 127, ws = t >> 7;
    const float* Wp = W + (size_t)o * Dd * Ee + e;
    float acc = 0.f;
#pragma unroll 16
    for (int dd = 0; dd < 256; dd++) {
        int d = ws * 256 + dd;
        acc += Us[d] * Wp[(size_t)d * Ee];
    }
    part[ws][e] = acc;
    __syncthreads();

    float v = 0.f;
    if (t < 128) {
        float s = (part[0][t] + part[1][t] + part[2][t] + part[3][t]) * (1.f / 6.f);
        v = s;
        float x = s * s;
#pragma unroll
        for (int sh = 16; sh; sh >>= 1) x += __shfl_xor_sync(0xffffffffu, x, sh);
        if ((t & 31) == 0) red[t >> 5] = x;
    }
    __syncthreads();
    if (t < 128) {
        float sq = red[0] + red[1] + red[2] + red[3];
        float f  = sq / (1.f + sq) / (sqrtf(sq) + 1e-8f);
        g_Vacc[(b * Oo + o) * Ee + t] = f * v;
    }
}

// ---------------------------------------------------------------------------
// K3: Wv[b,o,d] = sum_e W[o,d,e] * Vacc[b,o,e].  grid (128, O), 256 thr.
// ---------------------------------------------------------------------------
__global__ __launch_bounds__(256) void k_wv(const float* __restrict__ W) {
    __shared__ float4 Vs[Bb][32];
    int t = threadIdx.x, w = t >> 5, lane = t & 31;
    int o = blockIdx.y;

    {
        int b = t >> 5, i = t & 31;
        Vs[b][i] = reinterpret_cast<const float4*>(g_Vacc)[(b * Oo + o) * 32 + i];
    }
    __syncthreads();

    int d = blockIdx.x * 8 + w;
    float4 w4 = reinterpret_cast<const float4*>(W)[((size_t)o * Dd + d) * 32 + lane];

    float acc[8];
#pragma unroll
    for (int b = 0; b < 8; b++) {
        float4 v4 = Vs[b][lane];
        acc[b] = w4.x * v4.x + w4.y * v4.y + w4.z * v4.z + w4.w * v4.w;
    }
#pragma unroll
    for (int sh = 16; sh; sh >>= 1) {
#pragma unroll
        for (int b = 0; b < 8; b++)
            acc[b] += __shfl_xor_sync(0xffffffffu, acc[b], sh);
    }
    if (lane < 8)
        g_Wv[(lane * Oo + o) * Dd + d] = acc[lane];
}

// ---------------------------------------------------------------------------
// Shared softmax helper
// ---------------------------------------------------------------------------
__device__ __forceinline__ void softmax6(const float lg[6], bool masked, float p[6]) {
    if (masked) {
#pragma unroll
        for (int o = 0; o < 6; o++) p[o] = 1.f / 6.f;
    } else {
        float m = lg[0];
#pragma unroll
        for (int o = 1; o < 6; o++) m = fmaxf(m, lg[o]);
        float s = 0.f;
#pragma unroll
        for (int o = 0; o < 6; o++) { p[o] = expf(lg[o] - m); s += p[o]; }
        float inv = 1.f / s;
#pragma unroll
        for (int o = 0; o < 6; o++) p[o] *= inv;
    }
}

// ---------------------------------------------------------------------------
// K4 (iteration 1, ROUND-9 PROVEN): fused logits -> softmax -> probs -> Up.
// grid (K/32=32, B), 256 threads = 8 warps. Static 24KB smem, occ ~21%.
// ---------------------------------------------------------------------------
__global__ __launch_bounds__(256) void k_route(const float* __restrict__ u,
                                               const void*  __restrict__ maskp) {
    int t = threadIdx.x;
    int w = t >> 5, lane = t & 31;
    int b  = blockIdx.y;
    int k0 = blockIdx.x * 32;

    __shared__ __align__(16) float Wv_s[Oo * Dd];   // 24 KB
    __shared__ float probs_s[32 * Oo];

    {
        float4*       ds = reinterpret_cast<float4*>(Wv_s);
        const float4* ss = reinterpret_cast<const float4*>(g_Wv + (size_t)b * Oo * Dd);
#pragma unroll
        for (int i = 0; i < 6; i++) ds[t + 256 * i] = ss[t + 256 * i];
    }
    __syncthreads();

    // Phase 1: logits for 4 k per warp
    int kw = k0 + w * 4;
    float lg[4][6];
#pragma unroll
    for (int kk = 0; kk < 4; kk++)
#pragma unroll
        for (int o = 0; o < 6; o++) lg[kk][o] = 0.f;

    const float4* up4 = reinterpret_cast<const float4*>(u) + (size_t)(b * Kk + kw) * 256;
    const float4* wv4 = reinterpret_cast<const float4*>(Wv_s);
#pragma unroll
    for (int j = 0; j < 8; j++) {
        int di = j * 32 + lane;
        float4 wv[6];
#pragma unroll
        for (int o = 0; o < 6; o++) wv[o] = wv4[o * 256 + di];
#pragma unroll
        for (int kk = 0; kk < 4; kk++) {
            float4 uv = up4[(size_t)kk * 256 + di];
#pragma unroll
            for (int o = 0; o < 6; o++)
                lg[kk][o] += uv.x * wv[o].x + uv.y * wv[o].y
                           + uv.z * wv[o].z + uv.w * wv[o].w;
        }
    }
#pragma unroll
    for (int sh = 16; sh; sh >>= 1)
#pragma unroll
        for (int kk = 0; kk < 4; kk++)
#pragma unroll
            for (int o = 0; o < 6; o++)
                lg[kk][o] += __shfl_xor_sync(0xffffffffu, lg[kk][o], sh);

    int u8 = g_mask_u8;
    if (lane == 0) {
#pragma unroll
        for (int kk = 0; kk < 4; kk++) {
            int k = kw + kk;
            bool masked = u8 ? (((const unsigned char*)maskp)[b * Kk + k] != 0)
                             : (((const int*)maskp)[b * Kk + k] != 0);
            float p[6];
            softmax6(lg[kk], masked, p);
#pragma unroll
            for (int o = 0; o < 6; o++) probs_s[(w * 4 + kk) * 6 + o] = p[o];
        }
    }
    __syncthreads();

    if (t < 192) g_probs[(size_t)(b * Kk + k0) * 6 + t] = probs_s[t];

    // Phase 2: Up partials — thread owns float4 d-chunk t
    float4 acc4[6];
#pragma unroll
    for (int o = 0; o < 6; o++) acc4[o] = make_float4(0.f, 0.f, 0.f, 0.f);

    const float4* ub4 = reinterpret_cast<const float4*>(u) + (size_t)(b * Kk + k0) * 256;
#pragma unroll 4
    for (int kk = 0; kk < 32; kk++) {
        float4 uv = ub4[(size_t)kk * 256 + t];
        float pv[6];
#pragma unroll
        for (int o = 0; o < 6; o++) pv[o] = probs_s[kk * 6 + o];
#pragma unroll
        for (int o = 0; o < 6; o++) {
            acc4[o].x += pv[o] * uv.x;
            acc4[o].y += pv[o] * uv.y;
            acc4[o].z += pv[o] * uv.z;
            acc4[o].w += pv[o] * uv.w;
        }
    }
    float4* upp4 = reinterpret_cast<float4*>(
        g_UpP + ((size_t)(b * 32 + blockIdx.x) * Oo) * Dd);
#pragma unroll
    for (int o = 0; o < 6; o++) upp4[o * 256 + t] = acc4[o];
}

// ---------------------------------------------------------------------------
// K4b: logits-only route (iteration 2) — produces FINAL probs early so the
// 201MB probs broadcast can fork immediately.
// ---------------------------------------------------------------------------
__global__ __launch_bounds__(256) void k_route_logits(const float* __restrict__ u,
                                                      const void*  __restrict__ maskp) {
    int t = threadIdx.x;
    int w = t >> 5, lane = t & 31;
    int b  = blockIdx.y;
    int k0 = blockIdx.x * 32;

    __shared__ __align__(16) float Wv_s[Oo * Dd];
    __shared__ float probs_s[32 * Oo];

    {
        float4*       ds = reinterpret_cast<float4*>(Wv_s);
        const float4* ss = reinterpret_cast<const float4*>(g_Wv + (size_t)b * Oo * Dd);
#pragma unroll
        for (int i = 0; i < 6; i++) ds[t + 256 * i] = ss[t + 256 * i];
    }
    __syncthreads();

    int kw = k0 + w * 4;
    float lg[4][6];
#pragma unroll
    for (int kk = 0; kk < 4; kk++)
#pragma unroll
        for (int o = 0; o < 6; o++) lg[kk][o] = 0.f;

    const float4* up4 = reinterpret_cast<const float4*>(u) + (size_t)(b * Kk + kw) * 256;
    const float4* wv4 = reinterpret_cast<const float4*>(Wv_s);
#pragma unroll
    for (int j = 0; j < 8; j++) {
        int di = j * 32 + lane;
        float4 wv[6];
#pragma unroll
        for (int o = 0; o < 6; o++) wv[o] = wv4[o * 256 + di];
#pragma unroll
        for (int kk = 0; kk < 4; kk++) {
            float4 uv = up4[(size_t)kk * 256 + di];
#pragma unroll
            for (int o = 0; o < 6; o++)
                lg[kk][o] += uv.x * wv[o].x + uv.y * wv[o].y
                           + uv.z * wv[o].z + uv.w * wv[o].w;
        }
    }
#pragma unroll
    for (int sh = 16; sh; sh >>= 1)
#pragma unroll
        for (int kk = 0; kk < 4; kk++)
#pragma unroll
            for (int o = 0; o < 6; o++)
                lg[kk][o] += __shfl_xor_sync(0xffffffffu, lg[kk][o], sh);

    int u8 = g_mask_u8;
    if (lane == 0) {
#pragma unroll
        for (int kk = 0; kk < 4; kk++) {
            int k = kw + kk;
            bool masked = u8 ? (((const unsigned char*)maskp)[b * Kk + k] != 0)
                             : (((const int*)maskp)[b * Kk + k] != 0);
            float p[6];
            softmax6(lg[kk], masked, p);
#pragma unroll
            for (int o = 0; o < 6; o++) probs_s[(w * 4 + kk) * 6 + o] = p[o];
        }
    }
    __syncthreads();
    if (t < 192) g_probs[(size_t)(b * Kk + k0) * 6 + t] = probs_s[t];
}

// ---------------------------------------------------------------------------
// K4c: Up partials from stored probs (iteration 2, overlaps bcast_probs).
// ---------------------------------------------------------------------------
__global__ __launch_bounds__(256) void k_route_up(const float* __restrict__ u) {
    int t  = threadIdx.x;
    int b  = blockIdx.y;
    int k0 = blockIdx.x * 32;

    __shared__ float probs_s[32 * Oo];
    if (t < 192) probs_s[t] = g_probs[(size_t)(b * Kk + k0) * 6 + t];
    __syncthreads();

    float4 acc4[6];
#pragma unroll
    for (int o = 0; o < 6; o++) acc4[o] = make_float4(0.f, 0.f, 0.f, 0.f);

    const float4* ub4 = reinterpret_cast<const float4*>(u) + (size_t)(b * Kk + k0) * 256;
#pragma unroll 4
    for (int kk = 0; kk < 32; kk++) {
        float4 uv = ub4[(size_t)kk * 256 + t];
        float pv[6];
#pragma unroll
        for (int o = 0; o < 6; o++) pv[o] = probs_s[kk * 6 + o];
#pragma unroll
        for (int o = 0; o < 6; o++) {
            acc4[o].x += pv[o] * uv.x;
            acc4[o].y += pv[o] * uv.y;
            acc4[o].z += pv[o] * uv.z;
            acc4[o].w += pv[o] * uv.w;
        }
    }
    float4* upp4 = reinterpret_cast<float4*>(
        g_UpP + ((size_t)(b * 32 + blockIdx.x) * Oo) * Dd);
#pragma unroll
    for (int o = 0; o < 6; o++) upp4[o * 256 + t] = acc4[o];
}

// ---------------------------------------------------------------------------
// K6: v_i = squash(Up . W); Vacc += v_i; store v_i.  grid (O, B), 512 thr.
// ---------------------------------------------------------------------------
__global__ __launch_bounds__(512) void k_vi(const float* __restrict__ W) {
    int t = threadIdx.x;
    int o = blockIdx.x, b = blockIdx.y;
    __shared__ float Up_s[Dd];
    __shared__ float part[4][Ee];
    __shared__ float red[4];

    for (int d = t; d < Dd; d += 512) {
        float s = 0.f;
#pragma unroll 8
        for (int kt = 0; kt < 32; kt++)
            s += g_UpP[((size_t)(b * 32 + kt) * Oo + o) * Dd + d];
        Up_s[d] = s;
    }
    __syncthreads();

    int e = t & 127, ws = t >> 7;
    const float* Wp = W + (size_t)o * Dd * Ee + e;
    float acc = 0.f;
#pragma unroll 16
    for (int dd = 0; dd < 256; dd++) {
        int d = ws * 256 + dd;
        acc += Up_s[d] * Wp[(size_t)d * Ee];
    }
    part[ws][e] = acc;
    __syncthreads();

    float v = 0.f;
    if (t < 128) {
        float s = part[0][t] + part[1][t] + part[2][t] + part[3][t];
        v = s;
        float x = s * s;
#pragma unroll
        for (int sh = 16; sh; sh >>= 1) x += __shfl_xor_sync(0xffffffffu, x, sh);
        if ((t & 31) == 0) red[t >> 5] = x;
    }
    __syncthreads();
    if (t < 128) {
        float sq = red[0] + red[1] + red[2] + red[3];
        float f  = sq / (1.f + sq) / (sqrtf(sq) + 1e-8f);
        float vv = f * v;
        int idx = (b * Oo + o) * Ee + t;
        g_vcur[idx] = vv;
        g_Vacc[idx] += vv;
    }
}

// ---------------------------------------------------------------------------
// K7a: broadcast probs over L (201 MB). Register staging + streaming stores.
// ---------------------------------------------------------------------------
__global__ __launch_bounds__(256) void k_bcast_probs(float* __restrict__ out) {
    int t   = threadIdx.x;
    int blk = blockIdx.x;              // b * 128 + l-chunk
    int b   = blk >> 7;
    int l0  = (blk & 127) * 8;

    const float4* ps = reinterpret_cast<const float4*>(g_probs) + (size_t)b * 1536;
    float4 pr[6];
#pragma unroll
    for (int i = 0; i < 6; i++) pr[i] = __ldg(ps + t + 256 * i);

    float4* op = reinterpret_cast<float4*>(out + (size_t)Bb * Ll * Oo * Ee);
#pragma unroll
    for (int j = 0; j < 8; j++) {
        size_t bl = (size_t)b * Ll + l0 + j;
#pragma unroll
        for (int i = 0; i < 6; i++)
            __stcs(op + bl * 1536 + t + 256 * i, pr[i]);
    }
}

// ---------------------------------------------------------------------------
// K7b: broadcast outputs_v over L (25 MB).
// ---------------------------------------------------------------------------
__global__ __launch_bounds__(192) void k_bcast_v(float* __restrict__ out) {
    int t   = threadIdx.x;             // 0..191
    int blk = blockIdx.x;
    int b   = blk >> 7;
    int l0  = (blk & 127) * 8;

    float4 vv = __ldg(reinterpret_cast<const float4*>(g_vcur) + b * 192 + t);
    float4* ov = reinterpret_cast<float4*>(out);
#pragma unroll
    for (int j = 0; j < 8; j++)
        __stcs(ov + ((size_t)b * Ll + l0 + j) * 192 + t, vv);
}

// ---------------------------------------------------------------------------
// Launch. Fork-join: after the final logits kernel, the 201MB probs
// broadcast runs on a side stream concurrently with route_up -> vi ->
// bcast_v on the main stream.
// ---------------------------------------------------------------------------
extern "C" void kernel_launch(void* const* d_in, const int* in_sizes, int n_in,
                              void* d_out, int out_size) {
    const float* u    = (const float*)d_in[0];
    // d_in[1] = context_sequence: unused (only its shape L matters)
    const float* W    = (const float*)d_in[2];
    const void*  mask = d_in[3];
    float* out = (float*)d_out;

    static cudaStream_t s2 = nullptr;
    static cudaEvent_t  e1 = nullptr, e2 = nullptr;
    if (s2 == nullptr) {
        cudaStreamCreateWithFlags(&s2, cudaStreamNonBlocking);
        cudaEventCreateWithFlags(&e1, cudaEventDisableTiming);
        cudaEventCreateWithFlags(&e2, cudaEventDisableTiming);
    }

    k_usum<<<dim3(2, 8, 8), 128>>>(u, (const unsigned char*)mask);
    k_v0  <<<dim3(Oo, Bb), 512>>>(W);

    // Iteration 1 (proven fused route)
    k_wv   <<<dim3(Dd / 8, Oo), 256>>>(W);
    k_route<<<dim3(Kk / 32, Bb), 256>>>(u, mask);
    k_vi   <<<dim3(Oo, Bb), 512>>>(W);

    // Iteration 2: logits first, then fork.
    k_wv          <<<dim3(Dd / 8, Oo), 256>>>(W);
    k_route_logits<<<dim3(Kk / 32, Bb), 256>>>(u, mask);

    cudaEventRecord(e1, 0);
    cudaStreamWaitEvent(s2, e1, 0);
    k_bcast_probs<<<Bb * (Ll / 8), 256, 0, s2>>>(out);   // 201 MB, overlapped
    cudaEventRecord(e2, s2);

    k_route_up<<<dim3(Kk / 32, Bb), 256>>>(u);
    k_vi      <<<dim3(Oo, Bb), 512>>>(W);
    k_bcast_v <<<Bb * (Ll / 8), 192>>>(out);

    cudaStreamWaitEvent(0, e2, 0);   // join: output complete when graph ends
}

// round 13
// speedup vs baseline: 1.0953x; 1.0707x over previous
#include <cuda_runtime.h>
#include <cstdint>
#include <math.h>

// Problem constants: B=8, K=1024, L=1024, D=1024, O=6, E=128
#define Bb 8
#define Kk 1024
#define Ll 1024
#define Dd 1024
#define Oo 6
#define Ee 128

// ---------------------------------------------------------------------------
// Scratch (device globals: allocation-free, persistent).
// ---------------------------------------------------------------------------
__device__ __align__(16) float g_UsumP[Bb * 8 * Dd];
__device__ __align__(16) float g_Wv   [Bb * Oo * Dd];
__device__ __align__(16) float g_Vacc [Bb * Oo * Ee];
__device__ __align__(16) float g_vcur [Bb * Oo * Ee];
__device__ __align__(16) float g_probs[Bb * Kk * Oo];
__device__ __align__(16) float g_UpP  [Bb * 32 * Oo * Dd];
__device__ int g_mask_u8;

// ---------------------------------------------------------------------------
// K1: Usum partials + mask-dtype probe (block 0).
// ---------------------------------------------------------------------------
__global__ void k_usum(const float* __restrict__ u,
                       const unsigned char* __restrict__ m) {
    int t  = threadIdx.x;

    if (blockIdx.x == 0 && blockIdx.y == 0 && blockIdx.z == 0) {
        __shared__ int f;
        if (t == 0) f = 0;
        __syncthreads();
        int loc = 0;
        for (int p = t; p < Bb * Kk; p += blockDim.x)
            if ((p & 3) && m[p]) loc = 1;
        if (loc) atomicOr(&f, 1);
        __syncthreads();
        if (t == 0) g_mask_u8 = f;
    }

    int d4 = blockIdx.x * 128 + t;
    int ks = blockIdx.y;
    int b  = blockIdx.z;
    const float4* p = reinterpret_cast<const float4*>(u)
                    + ((size_t)(b * Kk + ks * 128)) * 256 + d4;
    float4 s = make_float4(0.f, 0.f, 0.f, 0.f);
#pragma unroll 8
    for (int k = 0; k < 128; k++) {
        float4 v = p[(size_t)k * 256];
        s.x += v.x; s.y += v.y; s.z += v.z; s.w += v.w;
    }
    reinterpret_cast<float4*>(g_UsumP)[(b * 8 + ks) * 256 + d4] = s;
}

// ---------------------------------------------------------------------------
// K2: v0 = squash((1/6) * Usum . W).  grid (O, B), 512 threads.
// ---------------------------------------------------------------------------
__global__ __launch_bounds__(512) void k_v0(const float* __restrict__ W) {
    int t = threadIdx.x;
    int o = blockIdx.x, b = blockIdx.y;
    __shared__ float Us[Dd];
    __shared__ float part[4][Ee];
    __shared__ float red[4];

    for (int d = t; d < Dd; d += 512) {
        float s = 0.f;
#pragma unroll
        for (int ks = 0; ks < 8; ks++) s += g_UsumP[(b * 8 + ks) * Dd + d];
        Us[d] = s;
    }
    __syncthreads();

    int e = t & 127, ws = t >> 7;
    const float* Wp = W + (size_t)o * Dd * Ee + e;
    float acc = 0.f;
#pragma unroll 16
    for (int dd = 0; dd < 256; dd++) {
        int d = ws * 256 + dd;
        acc += Us[d] * Wp[(size_t)d * Ee];
    }
    part[ws][e] = acc;
    __syncthreads();

    float v = 0.f;
    if (t < 128) {
        float s = (part[0][t] + part[1][t] + part[2][t] + part[3][t]) * (1.f / 6.f);
        v = s;
        float x = s * s;
#pragma unroll
        for (int sh = 16; sh; sh >>= 1) x += __shfl_xor_sync(0xffffffffu, x, sh);
        if ((t & 31) == 0) red[t >> 5] = x;
    }
    __syncthreads();
    if (t < 128) {
        float sq = red[0] + red[1] + red[2] + red[3];
        float f  = sq / (1.f + sq) / (sqrtf(sq) + 1e-8f);
        g_Vacc[(b * Oo + o) * Ee + t] = f * v;
    }
}

// ---------------------------------------------------------------------------
// K3 (REWRITTEN): Wv[b,o,d] = sum_e W[o,d,e] * Vacc[b,o,e].
// grid (Dd/32=32, Oo), 256 threads. Block stages a 32-row W tile (16KB,
// coalesced float4, 4 loads/thread = MLP 4) + all 8 Vacc vectors, then
// thread (b = t>>5, d = t&31) dots entirely from smem. Padded stride kills
// LDS conflicts (quarter-warp phases see 8 distinct bank groups).
// ---------------------------------------------------------------------------
__global__ __launch_bounds__(256) void k_wv(const float* __restrict__ W) {
    __shared__ __align__(16) float4 Ws[32][33];   // +1 float4 pad
    __shared__ float4 Vs[Bb][32];
    int t = threadIdx.x;
    int o = blockIdx.y;
    int d0 = blockIdx.x * 32;

    const float4* Wg = reinterpret_cast<const float4*>(W) + ((size_t)o * Dd + d0) * 32;
#pragma unroll
    for (int i = 0; i < 4; i++) {
        int idx = t + 256 * i;            // 0..1023
        Ws[idx >> 5][idx & 31] = Wg[idx];
    }
    {
        int b = t >> 5, col = t & 31;
        Vs[b][col] = reinterpret_cast<const float4*>(g_Vacc)[(b * Oo + o) * 32 + col];
    }
    __syncthreads();

    int dl = t & 31, b = t >> 5;          // warp b, lane d
    float acc = 0.f;
#pragma unroll
    for (int e4 = 0; e4 < 32; e4++) {
        float4 w4 = Ws[dl][e4];
        float4 v4 = Vs[b][e4];            // broadcast within warp
        acc += w4.x * v4.x + w4.y * v4.y + w4.z * v4.z + w4.w * v4.w;
    }
    g_Wv[(b * Oo + o) * Dd + d0 + dl] = acc;
}

// ---------------------------------------------------------------------------
// Shared softmax helper
// ---------------------------------------------------------------------------
__device__ __forceinline__ void softmax6(const float lg[6], bool masked, float p[6]) {
    if (masked) {
#pragma unroll
        for (int o = 0; o < 6; o++) p[o] = 1.f / 6.f;
    } else {
        float m = lg[0];
#pragma unroll
        for (int o = 1; o < 6; o++) m = fmaxf(m, lg[o]);
        float s = 0.f;
#pragma unroll
        for (int o = 0; o < 6; o++) { p[o] = expf(lg[o] - m); s += p[o]; }
        float inv = 1.f / s;
#pragma unroll
        for (int o = 0; o < 6; o++) p[o] *= inv;
    }
}

// ---------------------------------------------------------------------------
// K4 (R9-proven): fused logits -> softmax -> probs -> Up partials.
// grid (K/32=32, B), 256 threads = 8 warps.
// ---------------------------------------------------------------------------
__global__ __launch_bounds__(256) void k_route(const float* __restrict__ u,
                                               const void*  __restrict__ maskp) {
    int t = threadIdx.x;
    int w = t >> 5, lane = t & 31;
    int b  = blockIdx.y;
    int k0 = blockIdx.x * 32;

    __shared__ __align__(16) float Wv_s[Oo * Dd];   // 24 KB
    __shared__ float probs_s[32 * Oo];

    {
        float4*       ds = reinterpret_cast<float4*>(Wv_s);
        const float4* ss = reinterpret_cast<const float4*>(g_Wv + (size_t)b * Oo * Dd);
#pragma unroll
        for (int i = 0; i < 6; i++) ds[t + 256 * i] = ss[t + 256 * i];
    }
    __syncthreads();

    int kw = k0 + w * 4;
    float lg[4][6];
#pragma unroll
    for (int kk = 0; kk < 4; kk++)
#pragma unroll
        for (int o = 0; o < 6; o++) lg[kk][o] = 0.f;

    const float4* up4 = reinterpret_cast<const float4*>(u) + (size_t)(b * Kk + kw) * 256;
    const float4* wv4 = reinterpret_cast<const float4*>(Wv_s);
#pragma unroll
    for (int j = 0; j < 8; j++) {
        int di = j * 32 + lane;
        float4 wv[6];
#pragma unroll
        for (int o = 0; o < 6; o++) wv[o] = wv4[o * 256 + di];
#pragma unroll
        for (int kk = 0; kk < 4; kk++) {
            float4 uv = up4[(size_t)kk * 256 + di];
#pragma unroll
            for (int o = 0; o < 6; o++)
                lg[kk][o] += uv.x * wv[o].x + uv.y * wv[o].y
                           + uv.z * wv[o].z + uv.w * wv[o].w;
        }
    }
#pragma unroll
    for (int sh = 16; sh; sh >>= 1)
#pragma unroll
        for (int kk = 0; kk < 4; kk++)
#pragma unroll
            for (int o = 0; o < 6; o++)
                lg[kk][o] += __shfl_xor_sync(0xffffffffu, lg[kk][o], sh);

    int u8 = g_mask_u8;
    if (lane == 0) {
#pragma unroll
        for (int kk = 0; kk < 4; kk++) {
            int k = kw + kk;
            bool masked = u8 ? (((const unsigned char*)maskp)[b * Kk + k] != 0)
                             : (((const int*)maskp)[b * Kk + k] != 0);
            float p[6];
            softmax6(lg[kk], masked, p);
#pragma unroll
            for (int o = 0; o < 6; o++) probs_s[(w * 4 + kk) * 6 + o] = p[o];
        }
    }
    __syncthreads();

    if (t < 192) g_probs[(size_t)(b * Kk + k0) * 6 + t] = probs_s[t];

    float4 acc4[6];
#pragma unroll
    for (int o = 0; o < 6; o++) acc4[o] = make_float4(0.f, 0.f, 0.f, 0.f);

    const float4* ub4 = reinterpret_cast<const float4*>(u) + (size_t)(b * Kk + k0) * 256;
#pragma unroll 4
    for (int kk = 0; kk < 32; kk++) {
        float4 uv = ub4[(size_t)kk * 256 + t];
        float pv[6];
#pragma unroll
        for (int o = 0; o < 6; o++) pv[o] = probs_s[kk * 6 + o];
#pragma unroll
        for (int o = 0; o < 6; o++) {
            acc4[o].x += pv[o] * uv.x;
            acc4[o].y += pv[o] * uv.y;
            acc4[o].z += pv[o] * uv.z;
            acc4[o].w += pv[o] * uv.w;
        }
    }
    float4* upp4 = reinterpret_cast<float4*>(
        g_UpP + ((size_t)(b * 32 + blockIdx.x) * Oo) * Dd);
#pragma unroll
    for (int o = 0; o < 6; o++) upp4[o * 256 + t] = acc4[o];
}

// ---------------------------------------------------------------------------
// K6: v_i = squash(Up . W); Vacc += v_i; store v_i.  grid (O, B), 512 thr.
// ---------------------------------------------------------------------------
__global__ __launch_bounds__(512) void k_vi(const float* __restrict__ W) {
    int t = threadIdx.x;
    int o = blockIdx.x, b = blockIdx.y;
    __shared__ float Up_s[Dd];
    __shared__ float part[4][Ee];
    __shared__ float red[4];

    for (int d = t; d < Dd; d += 512) {
        float s = 0.f;
#pragma unroll 8
        for (int kt = 0; kt < 32; kt++)
            s += g_UpP[((size_t)(b * 32 + kt) * Oo + o) * Dd + d];
        Up_s[d] = s;
    }
    __syncthreads();

    int e = t & 127, ws = t >> 7;
    const float* Wp = W + (size_t)o * Dd * Ee + e;
    float acc = 0.f;
#pragma unroll 16
    for (int dd = 0; dd < 256; dd++) {
        int d = ws * 256 + dd;
        acc += Up_s[d] * Wp[(size_t)d * Ee];
    }
    part[ws][e] = acc;
    __syncthreads();

    float v = 0.f;
    if (t < 128) {
        float s = part[0][t] + part[1][t] + part[2][t] + part[3][t];
        v = s;
        float x = s * s;
#pragma unroll
        for (int sh = 16; sh; sh >>= 1) x += __shfl_xor_sync(0xffffffffu, x, sh);
        if ((t & 31) == 0) red[t >> 5] = x;
    }
    __syncthreads();
    if (t < 128) {
        float sq = red[0] + red[1] + red[2] + red[3];
        float f  = sq / (1.f + sq) / (sqrtf(sq) + 1e-8f);
        float vv = f * v;
        int idx = (b * Oo + o) * Ee + t;
        g_vcur[idx] = vv;
        g_Vacc[idx] += vv;
    }
}

// ---------------------------------------------------------------------------
// K7a: broadcast probs over L (201 MB). Register staging + streaming stores.
// ---------------------------------------------------------------------------
__global__ __launch_bounds__(256) void k_bcast_probs(float* __restrict__ out) {
    int t   = threadIdx.x;
    int blk = blockIdx.x;
    int b   = blk >> 7;
    int l0  = (blk & 127) * 8;

    const float4* ps = reinterpret_cast<const float4*>(g_probs) + (size_t)b * 1536;
    float4 pr[6];
#pragma unroll
    for (int i = 0; i < 6; i++) pr[i] = __ldg(ps + t + 256 * i);

    float4* op = reinterpret_cast<float4*>(out + (size_t)Bb * Ll * Oo * Ee);
#pragma unroll
    for (int j = 0; j < 8; j++) {
        size_t bl = (size_t)b * Ll + l0 + j;
#pragma unroll
        for (int i = 0; i < 6; i++)
            __stcs(op + bl * 1536 + t + 256 * i, pr[i]);
    }
}

// ---------------------------------------------------------------------------
// K7b: broadcast outputs_v over L (25 MB).
// ---------------------------------------------------------------------------
__global__ __launch_bounds__(192) void k_bcast_v(float* __restrict__ out) {
    int t   = threadIdx.x;
    int blk = blockIdx.x;
    int b   = blk >> 7;
    int l0  = (blk & 127) * 8;

    float4 vv = __ldg(reinterpret_cast<const float4*>(g_vcur) + b * 192 + t);
    float4* ov = reinterpret_cast<float4*>(out);
#pragma unroll
    for (int j = 0; j < 8; j++)
        __stcs(ov + ((size_t)b * Ll + l0 + j) * 192 + t, vv);
}

// ---------------------------------------------------------------------------
// Launch. R9 structure; the ONLY overlap is the zero-extra-work fork after
// the fused route2 (which already produced final probs): side stream does
// the 201MB probs broadcast while main runs vi2 -> bcast_v.
// ---------------------------------------------------------------------------
extern "C" void kernel_launch(void* const* d_in, const int* in_sizes, int n_in,
                              void* d_out, int out_size) {
    const float* u    = (const float*)d_in[0];
    // d_in[1] = context_sequence: unused (only its shape L matters)
    const float* W    = (const float*)d_in[2];
    const void*  mask = d_in[3];
    float* out = (float*)d_out;

    static cudaStream_t s2 = nullptr;
    static cudaEvent_t  e1 = nullptr, e2 = nullptr;
    if (s2 == nullptr) {
        cudaStreamCreateWithFlags(&s2, cudaStreamNonBlocking);
        cudaEventCreateWithFlags(&e1, cudaEventDisableTiming);
        cudaEventCreateWithFlags(&e2, cudaEventDisableTiming);
    }

    k_usum<<<dim3(2, 8, 8), 128>>>(u, (const unsigned char*)mask);
    k_v0  <<<dim3(Oo, Bb), 512>>>(W);

    // Iteration 1
    k_wv   <<<dim3(Dd / 32, Oo), 256>>>(W);
    k_route<<<dim3(Kk / 32, Bb), 256>>>(u, mask);
    k_vi   <<<dim3(Oo, Bb), 512>>>(W);

    // Iteration 2 (fused route writes final probs + UpP)
    k_wv   <<<dim3(Dd / 32, Oo), 256>>>(W);
    k_route<<<dim3(Kk / 32, Bb), 256>>>(u, mask);

    // Fork: probs broadcast (depends only on g_probs) overlaps vi2 + bcast_v.
    cudaEventRecord(e1, 0);
    cudaStreamWaitEvent(s2, e1, 0);
    k_bcast_probs<<<Bb * (Ll / 8), 256, 0, s2>>>(out);
    cudaEventRecord(e2, s2);

    k_vi     <<<dim3(Oo, Bb), 512>>>(W);
    k_bcast_v<<<Bb * (Ll / 8), 192>>>(out);

    cudaStreamWaitEvent(0, e2, 0);
}